// round 8
// baseline (speedup 1.0000x reference)
#include <cuda_runtime.h>

#define TILE 32
#define RAD 5
#define LT 42            // TILE + 2*RAD
#define IP 43            // sPQ pitch (u64 units); conflict-free h-window reads
#define HP 33            // h-buffer pitch (u64 units); odd -> conflict-free
#define IMG 512
#define NT 256
#define GRID1D 16
#define NBLK (GRID1D * GRID1D * 96)

typedef unsigned long long u64;

__device__ float g_part[NBLK];
__device__ int   g_ticket;

__device__ __forceinline__ u64 pk2(float x, float y) {
    u64 r; asm("mov.b64 %0,{%1,%2};" : "=l"(r) : "f"(x), "f"(y)); return r;
}
__device__ __forceinline__ void upk2(u64 v, float& x, float& y) {
    asm("mov.b64 {%0,%1},%2;" : "=f"(x), "=f"(y) : "l"(v));
}
__device__ __forceinline__ u64 fma2(u64 a, u64 b, u64 c) {
    u64 d; asm("fma.rn.f32x2 %0,%1,%2,%3;" : "=l"(d) : "l"(a), "l"(b), "l"(c)); return d;
}
__device__ __forceinline__ u64 mul2(u64 a, u64 b) {
    u64 d; asm("mul.rn.f32x2 %0,%1,%2;" : "=l"(d) : "l"(a), "l"(b)); return d;
}

__global__ __launch_bounds__(NT, 5) void ssim_kernel(
        const float* __restrict__ A, const float* __restrict__ B,
        float* __restrict__ out, int nblk, float inv_n) {
    // Gaussian(sigma=1.5, 11 taps); symmetric -> 6 unique packed weights after CSE
    constexpr float WGT[11] = {
        0.00102836f, 0.00759876f, 0.03600077f, 0.10936070f, 0.21300554f,
        0.26601172f,
        0.21300554f, 0.10936070f, 0.03600077f, 0.00759876f, 0.00102836f };

    __shared__ u64 sPQ[LT * IP];    // packed (p,q) = (x+y, x-y)        14.4 KB
    __shared__ u64 hPQ[LT * HP];    // conv_h(p,q)                      11.1 KB
    __shared__ u64 hSD[LT * HP];    // conv_h(p^2,q^2)                  11.1 KB
    __shared__ float wsum[NT / 32];
    __shared__ int   sLast;

    const int tid = threadIdx.x;
    const int tx  = tid & 31;
    const int wid = tid >> 5;
    const int x0 = blockIdx.x * TILE - RAD;
    const int y0 = blockIdx.y * TILE - RAD;
    const size_t planeOff = (size_t)blockIdx.z * (IMG * IMG);
    const float* __restrict__ pa = A + planeOff;
    const float* __restrict__ pb = B + planeOff;

    // ---- load halo tile (2D, predicated), build packed (p,q) ----
    #pragma unroll
    for (int rr = 0; rr < 6; rr++) {
        int r = wid + rr * 8;
        if (r < LT) {
            int gy = y0 + r;
            bool rowok = (unsigned)gy < IMG;
            const float* rowa = pa + gy * IMG;
            const float* rowb = pb + gy * IMG;
            int gx = x0 + tx;
            float va = 0.f, vb = 0.f;
            if (rowok && (unsigned)gx < IMG) { va = rowa[gx]; vb = rowb[gx]; }
            sPQ[r * IP + tx] = pk2(va + vb, va - vb);
            if (tx < LT - 32) {
                int gx2 = gx + 32;
                float wa = 0.f, wb = 0.f;
                if (rowok && (unsigned)gx2 < IMG) { wa = rowa[gx2]; wb = rowb[gx2]; }
                sPQ[r * IP + tx + 32] = pk2(wa + wb, wa - wb);
            }
        }
    }
    __syncthreads();

    // ---- horizontal pass: tasks tid and (tid+256 | tid<80), 4 output cols each ----
    {
        int g = tid;
        #pragma unroll
        for (int pass = 0; pass < 2; pass++) {
            if (pass == 0 || tid < (LT * 8 - NT)) {
                int r  = g >> 3;
                int c0 = (g & 7) * 4;
                const u64* rw = &sPQ[r * IP + c0];
                u64 m[4] = {0,0,0,0};
                u64 s[4] = {0,0,0,0};
                #pragma unroll
                for (int k = 0; k < 14; k++) {
                    u64 v  = rw[k];
                    u64 vv = mul2(v, v);
                    #pragma unroll
                    for (int u = 0; u < 4; u++) {
                        int t = k - u;
                        if (t >= 0 && t < 11) {
                            u64 w = pk2(WGT[t], WGT[t]);
                            m[u] = fma2(w, v,  m[u]);
                            s[u] = fma2(w, vv, s[u]);
                        }
                    }
                }
                #pragma unroll
                for (int u = 0; u < 4; u++) {
                    hPQ[r * HP + c0 + u] = m[u];
                    hSD[r * HP + c0 + u] = s[u];
                }
            }
            g = tid + NT;
        }
    }
    __syncthreads();

    // ---- vertical pass + SSIM: one column/thread, 4 consecutive rows ----
    const int r0v = wid * 4;
    u64 M[4] = {0,0,0,0};
    u64 S[4] = {0,0,0,0};
    #pragma unroll
    for (int k = 0; k < 14; k++) {
        u64 a = hPQ[(r0v + k) * HP + tx];
        u64 b = hSD[(r0v + k) * HP + tx];
        #pragma unroll
        for (int u = 0; u < 4; u++) {
            int t = k - u;
            if (t >= 0 && t < 11) {
                u64 w = pk2(WGT[t], WGT[t]);
                M[u] = fma2(w, a, M[u]);
                S[u] = fma2(w, b, S[u]);
            }
        }
    }

    float acc = 0.f;
    const float C1 = 1e-4f;   // 0.01^2
    const float C2 = 9e-4f;   // 0.03^2
    #pragma unroll
    for (int u = 0; u < 4; u++) {
        float Mp, Mq, Sp, Sq;
        upk2(M[u], Mp, Mq);
        upk2(S[u], Sp, Sq);
        float Mp2 = Mp * Mp, Mq2 = Mq * Mq;
        float Ep = Sp - Mp2;
        float Eq = Sq - Mq2;
        float num = (0.5f * (Mp2 - Mq2) + C1) * (0.5f * (Ep - Eq) + C2);
        float den = (0.5f * (Mp2 + Mq2) + C1) * (0.5f * (Ep + Eq) + C2);
        acc += __fdividef(num, den);
    }

    // ---- block reduction -> per-block partial ----
    #pragma unroll
    for (int o = 16; o > 0; o >>= 1)
        acc += __shfl_xor_sync(0xffffffffu, acc, o);
    if (tx == 0) wsum[wid] = acc;
    __syncthreads();

    const int bid = (blockIdx.z * GRID1D + blockIdx.y) * GRID1D + blockIdx.x;
    if (tid == 0) {
        float t = 0.f;
        #pragma unroll
        for (int wi = 0; wi < NT / 32; wi++) t += wsum[wi];
        g_part[bid] = t;
        __threadfence();
        int old = atomicAdd(&g_ticket, 1);
        sLast = (old == nblk - 1) ? 1 : 0;
    }
    __syncthreads();

    // ---- last block reduces all partials (reuse hPQ as double scratch) ----
    if (sLast) {
        double* sred = reinterpret_cast<double*>(hPQ);
        double s = 0.0;
        for (int i = tid; i < nblk; i += NT) s += (double)g_part[i];
        sred[tid] = s;
        __syncthreads();
        #pragma unroll
        for (int o = NT / 2; o > 0; o >>= 1) {
            if (tid < o) sred[tid] += sred[tid + o];
            __syncthreads();
        }
        if (tid == 0) {
            out[0] = (float)(1.0 - sred[0] * (double)inv_n);
            g_ticket = 0;   // reset for next graph replay
        }
    }
}

extern "C" void kernel_launch(void* const* d_in, const int* in_sizes, int n_in,
                              void* d_out, int out_size) {
    const float* A = (const float*)d_in[0];   // clean
    const float* B = (const float*)d_in[1];   // adversarial
    float* out = (float*)d_out;
    long long total = (long long)in_sizes[0];
    int planes = (int)(total / (IMG * IMG));  // 96
    int nblk = GRID1D * GRID1D * planes;

    dim3 grid(GRID1D, GRID1D, planes);
    ssim_kernel<<<grid, NT>>>(A, B, out, nblk, 1.0f / (float)total);
}

// round 9
// speedup vs baseline: 1.3448x; 1.3448x over previous
#include <cuda_runtime.h>

#define TILE 32
#define RAD 5
#define LT 42            // TILE + 2*RAD
#define IP 43            // sPQ pitch (u64 units); conflict-free h-window reads
#define HP 33            // h-buffer pitch (u64 units); odd -> conflict-free
#define IMG 512
#define NT 256
#define GRID1D 16

typedef unsigned long long u64;

__device__ double g_sum;   // zero-initialized; epilogue resets after each use

__device__ __forceinline__ u64 pk2(float x, float y) {
    u64 r; asm("mov.b64 %0,{%1,%2};" : "=l"(r) : "f"(x), "f"(y)); return r;
}
__device__ __forceinline__ void upk2(u64 v, float& x, float& y) {
    asm("mov.b64 {%0,%1},%2;" : "=f"(x), "=f"(y) : "l"(v));
}
__device__ __forceinline__ u64 fma2(u64 a, u64 b, u64 c) {
    u64 d; asm("fma.rn.f32x2 %0,%1,%2,%3;" : "=l"(d) : "l"(a), "l"(b), "l"(c)); return d;
}
__device__ __forceinline__ u64 mul2(u64 a, u64 b) {
    u64 d; asm("mul.rn.f32x2 %0,%1,%2;" : "=l"(d) : "l"(a), "l"(b)); return d;
}

__global__ __launch_bounds__(NT) void ssim_kernel(
        const float* __restrict__ A, const float* __restrict__ B) {
    // Gaussian(sigma=1.5, 11 taps), normalized
    constexpr float WGT[11] = {
        0.00102836f, 0.00759876f, 0.03600077f, 0.10936070f, 0.21300554f,
        0.26601172f,
        0.21300554f, 0.10936070f, 0.03600077f, 0.00759876f, 0.00102836f };

    __shared__ u64 sPQ[LT * IP];   // packed (p,q) = (x+y, x-y)
    __shared__ u64 hPQ[LT * HP];   // conv_h(p,q)
    __shared__ u64 hSD[LT * HP];   // conv_h(p^2,q^2)
    __shared__ float wsum[NT / 32];

    const int tid = threadIdx.x;
    const int x0 = blockIdx.x * TILE - RAD;
    const int y0 = blockIdx.y * TILE - RAD;
    const size_t planeOff = (size_t)blockIdx.z * (IMG * IMG);
    const float* __restrict__ pa = A + planeOff;
    const float* __restrict__ pb = B + planeOff;

    // ---- load halo tile, build (p,q) packed; zero padding outside image ----
    for (int i = tid; i < LT * LT; i += NT) {
        int r = i / LT;
        int c = i - r * LT;
        int gy = y0 + r, gx = x0 + c;
        float va = 0.f, vb = 0.f;
        if ((unsigned)gy < IMG && (unsigned)gx < IMG) {
            va = pa[gy * IMG + gx];
            vb = pb[gy * IMG + gx];
        }
        sPQ[r * IP + c] = pk2(va + vb, va - vb);
    }
    __syncthreads();

    // ---- horizontal pass: 42 rows x 8 col-groups, 4 consecutive output cols/thread ----
    for (int g = tid; g < LT * (TILE / 4); g += NT) {
        int cg = g & 7;
        int r = g >> 3;
        int c0 = cg * 4;
        const u64* row = &sPQ[r * IP + c0];
        u64 m[4] = {0,0,0,0};   // conv_h(p,q)
        u64 s[4] = {0,0,0,0};   // conv_h(p^2,q^2)
        #pragma unroll
        for (int k = 0; k < 14; k++) {
            u64 v  = row[k];
            u64 vv = mul2(v, v);
            #pragma unroll
            for (int u = 0; u < 4; u++) {
                int t = k - u;
                if (t >= 0 && t < 11) {
                    u64 w = pk2(WGT[t], WGT[t]);
                    m[u] = fma2(w, v,  m[u]);
                    s[u] = fma2(w, vv, s[u]);
                }
            }
        }
        #pragma unroll
        for (int u = 0; u < 4; u++) {
            hPQ[r * HP + c0 + u] = m[u];
            hSD[r * HP + c0 + u] = s[u];
        }
    }
    __syncthreads();

    // ---- vertical pass + SSIM: one column per thread, 4 consecutive rows ----
    const int c  = tid & 31;
    const int r0 = (tid >> 5) * 4;
    u64 M[4] = {0,0,0,0};
    u64 S[4] = {0,0,0,0};
    #pragma unroll
    for (int k = 0; k < 14; k++) {
        int row = r0 + k;
        u64 a = hPQ[row * HP + c];
        u64 b = hSD[row * HP + c];
        #pragma unroll
        for (int u = 0; u < 4; u++) {
            int t = k - u;
            if (t >= 0 && t < 11) {
                u64 w = pk2(WGT[t], WGT[t]);
                M[u] = fma2(w, a, M[u]);
                S[u] = fma2(w, b, S[u]);
            }
        }
    }

    float acc = 0.f;
    const float C1 = 1e-4f;   // 0.01^2
    const float C2 = 9e-4f;   // 0.03^2
    #pragma unroll
    for (int u = 0; u < 4; u++) {
        float Mp, Mq, Sp, Sq;
        upk2(M[u], Mp, Mq);
        upk2(S[u], Sp, Sq);
        float Mp2 = Mp * Mp, Mq2 = Mq * Mq;
        float Ep = Sp - Mp2;       // conv(p^2) - Mp^2
        float Eq = Sq - Mq2;
        // mu12 = (Mp2-Mq2)/4 ; mu1^2+mu2^2 = (Mp2+Mq2)/2
        // sig12 = (Ep-Eq)/4  ; sig1^2+sig2^2 = (Ep+Eq)/2
        float num = (0.5f * (Mp2 - Mq2) + C1) * (0.5f * (Ep - Eq) + C2);
        float den = (0.5f * (Mp2 + Mq2) + C1) * (0.5f * (Ep + Eq) + C2);
        acc += __fdividef(num, den);
    }

    // ---- block reduction -> one double red.add per block (overlapped, no fence) ----
    #pragma unroll
    for (int o = 16; o > 0; o >>= 1)
        acc += __shfl_xor_sync(0xffffffffu, acc, o);
    if ((tid & 31) == 0) wsum[tid >> 5] = acc;
    __syncthreads();
    if (tid == 0) {
        float t = 0.f;
        #pragma unroll
        for (int wi = 0; wi < NT / 32; wi++) t += wsum[wi];
        atomicAdd(&g_sum, (double)t);
    }
}

__global__ void final_kernel(float* out, double inv_n) {
    out[0] = (float)(1.0 - g_sum * inv_n);
    g_sum = 0.0;   // reset for the next replay (deterministic, same-stream ordering)
}

extern "C" void kernel_launch(void* const* d_in, const int* in_sizes, int n_in,
                              void* d_out, int out_size) {
    const float* A = (const float*)d_in[0];   // clean
    const float* B = (const float*)d_in[1];   // adversarial
    float* out = (float*)d_out;
    long long total = (long long)in_sizes[0];
    int planes = (int)(total / (IMG * IMG));  // 96 = 32*3

    dim3 grid(GRID1D, GRID1D, planes);
    ssim_kernel<<<grid, NT>>>(A, B);
    final_kernel<<<1, 1>>>(out, 1.0 / (double)total);
}

// round 14
// speedup vs baseline: 1.3932x; 1.0360x over previous
#include <cuda_runtime.h>

#define TILE 32
#define RAD 5
#define LT 42            // TILE + 2*RAD
#define IP 43            // sPQ pitch (u64 units); conflict-free h-window reads
#define HP 33            // h-buffer pitch (u64 units); odd -> conflict-free v reads
#define IMG 512
#define NT 256
#define GRID1D 16

typedef unsigned long long u64;

__device__ double g_sum;   // zero-initialized; epilogue resets after each use

__device__ __forceinline__ u64 pk2(float x, float y) {
    u64 r; asm("mov.b64 %0,{%1,%2};" : "=l"(r) : "f"(x), "f"(y)); return r;
}
__device__ __forceinline__ void upk2(u64 v, float& x, float& y) {
    asm("mov.b64 {%0,%1},%2;" : "=f"(x), "=f"(y) : "l"(v));
}
__device__ __forceinline__ u64 fma2(u64 a, u64 b, u64 c) {
    u64 d; asm("fma.rn.f32x2 %0,%1,%2,%3;" : "=l"(d) : "l"(a), "l"(b), "l"(c)); return d;
}
__device__ __forceinline__ u64 mul2(u64 a, u64 b) {
    u64 d; asm("mul.rn.f32x2 %0,%1,%2;" : "=l"(d) : "l"(a), "l"(b)); return d;
}

__global__ __launch_bounds__(NT, 6) void ssim_kernel(
        const float* __restrict__ A, const float* __restrict__ B) {
    // Gaussian(sigma=1.5, 11 taps), normalized; symmetric -> 6 unique packed weights
    constexpr float WGT[11] = {
        0.00102836f, 0.00759876f, 0.03600077f, 0.10936070f, 0.21300554f,
        0.26601172f,
        0.21300554f, 0.10936070f, 0.03600077f, 0.00759876f, 0.00102836f };

    __shared__ u64 sPQ[LT * IP];   // packed (p,q) = (x+y, x-y)   14.4 KB
    __shared__ u64 hPQ[LT * HP];   // conv_h(p,q)                 11.1 KB
    __shared__ u64 hSD[LT * HP];   // conv_h(p^2,q^2)             11.1 KB
    __shared__ float wsum[NT / 32];

    const int tid = threadIdx.x;
    const int tx  = tid & 31;
    const int wid = tid >> 5;
    const int x0 = blockIdx.x * TILE - RAD;
    const int y0 = blockIdx.y * TILE - RAD;
    const size_t planeOff = (size_t)blockIdx.z * (IMG * IMG);
    const float* __restrict__ pa = A + planeOff;
    const float* __restrict__ pb = B + planeOff;

    // ---- load halo tile (2D; interior blocks skip all bounds checks) ----
    const bool interior = (x0 >= 0) & (y0 >= 0) &
                          (x0 + LT <= IMG) & (y0 + LT <= IMG);
    if (interior) {
        #pragma unroll
        for (int rr = 0; rr < 6; rr++) {
            int r = wid + rr * 8;
            if (rr < 5 || r < LT) {
                const float* rowa = pa + (y0 + r) * IMG + x0;
                const float* rowb = pb + (y0 + r) * IMG + x0;
                float va = rowa[tx], vb = rowb[tx];
                sPQ[r * IP + tx] = pk2(va + vb, va - vb);
                if (tx < LT - 32) {
                    float wa = rowa[tx + 32], wb = rowb[tx + 32];
                    sPQ[r * IP + tx + 32] = pk2(wa + wb, wa - wb);
                }
            }
        }
    } else {
        #pragma unroll
        for (int rr = 0; rr < 6; rr++) {
            int r = wid + rr * 8;
            if (rr < 5 || r < LT) {
                int gy = y0 + r;
                bool rowok = (unsigned)gy < IMG;
                const float* rowa = pa + gy * IMG;
                const float* rowb = pb + gy * IMG;
                int gx = x0 + tx;
                float va = 0.f, vb = 0.f;
                if (rowok && (unsigned)gx < IMG) { va = rowa[gx]; vb = rowb[gx]; }
                sPQ[r * IP + tx] = pk2(va + vb, va - vb);
                if (tx < LT - 32) {
                    int gx2 = gx + 32;
                    float wa = 0.f, wb = 0.f;
                    if (rowok && (unsigned)gx2 < IMG) { wa = rowa[gx2]; wb = rowb[gx2]; }
                    sPQ[r * IP + tx + 32] = pk2(wa + wb, wa - wb);
                }
            }
        }
    }
    __syncthreads();

    // ---- horizontal pass: static tasks tid and (tid+256 if tid<80) ----
    {
        int g = tid;
        #pragma unroll
        for (int pass = 0; pass < 2; pass++) {
            if (pass == 0 || tid < (LT * 8 - NT)) {
                int r  = g >> 3;
                int c0 = (g & 7) * 4;
                const u64* rw = &sPQ[r * IP + c0];
                u64 m[4] = {0,0,0,0};   // conv_h(p,q)
                u64 s[4] = {0,0,0,0};   // conv_h(p^2,q^2)
                #pragma unroll
                for (int k = 0; k < 14; k++) {
                    u64 v  = rw[k];
                    u64 vv = mul2(v, v);
                    #pragma unroll
                    for (int u = 0; u < 4; u++) {
                        int t = k - u;
                        if (t >= 0 && t < 11) {
                            u64 w = pk2(WGT[t], WGT[t]);
                            m[u] = fma2(w, v,  m[u]);
                            s[u] = fma2(w, vv, s[u]);
                        }
                    }
                }
                #pragma unroll
                for (int u = 0; u < 4; u++) {
                    hPQ[r * HP + c0 + u] = m[u];
                    hSD[r * HP + c0 + u] = s[u];
                }
            }
            g = tid + NT;
        }
    }
    __syncthreads();

    // ---- vertical pass + SSIM: one column per thread, 4 consecutive rows ----
    const int r0 = wid * 4;
    u64 M[4] = {0,0,0,0};
    u64 S[4] = {0,0,0,0};
    #pragma unroll
    for (int k = 0; k < 14; k++) {
        int row = r0 + k;
        u64 a = hPQ[row * HP + tx];
        u64 b = hSD[row * HP + tx];
        #pragma unroll
        for (int u = 0; u < 4; u++) {
            int t = k - u;
            if (t >= 0 && t < 11) {
                u64 w = pk2(WGT[t], WGT[t]);
                M[u] = fma2(w, a, M[u]);
                S[u] = fma2(w, b, S[u]);
            }
        }
    }

    float acc = 0.f;
    const float C1 = 1e-4f;   // 0.01^2
    const float C2 = 9e-4f;   // 0.03^2
    #pragma unroll
    for (int u = 0; u < 4; u++) {
        float Mp, Mq, Sp, Sq;
        upk2(M[u], Mp, Mq);
        upk2(S[u], Sp, Sq);
        float Mp2 = Mp * Mp, Mq2 = Mq * Mq;
        float Ep = Sp - Mp2;       // conv(p^2) - Mp^2
        float Eq = Sq - Mq2;
        // mu12 = (Mp2-Mq2)/4 ; mu1^2+mu2^2 = (Mp2+Mq2)/2
        // sig12 = (Ep-Eq)/4  ; sig1^2+sig2^2 = (Ep+Eq)/2
        float num = (0.5f * (Mp2 - Mq2) + C1) * (0.5f * (Ep - Eq) + C2);
        float den = (0.5f * (Mp2 + Mq2) + C1) * (0.5f * (Ep + Eq) + C2);
        acc += __fdividef(num, den);
    }

    // ---- block reduction -> one double red.add per block (overlapped, no fence) ----
    #pragma unroll
    for (int o = 16; o > 0; o >>= 1)
        acc += __shfl_xor_sync(0xffffffffu, acc, o);
    if (tx == 0) wsum[wid] = acc;
    __syncthreads();
    if (tid == 0) {
        float t = 0.f;
        #pragma unroll
        for (int wi = 0; wi < NT / 32; wi++) t += wsum[wi];
        atomicAdd(&g_sum, (double)t);
    }
}

__global__ void final_kernel(float* out, double inv_n) {
    out[0] = (float)(1.0 - g_sum * inv_n);
    g_sum = 0.0;   // reset for the next replay (same-stream ordering keeps this deterministic)
}

extern "C" void kernel_launch(void* const* d_in, const int* in_sizes, int n_in,
                              void* d_out, int out_size) {
    const float* A = (const float*)d_in[0];   // clean
    const float* B = (const float*)d_in[1];   // adversarial
    float* out = (float*)d_out;
    long long total = (long long)in_sizes[0];
    int planes = (int)(total / (IMG * IMG));  // 96 = 32*3

    dim3 grid(GRID1D, GRID1D, planes);
    ssim_kernel<<<grid, NT>>>(A, B);
    final_kernel<<<1, 1>>>(out, 1.0 / (double)total);
}